// round 5
// baseline (speedup 1.0000x reference)
#include <cuda_runtime.h>
#include <cuda_bf16.h>

#define BMAX 256

// scratch (channel-last where noted)
__device__ float g_p1t  [BMAX * 14 * 14 * 32];   // (b, h, w, c)
__device__ float g_off2t[BMAX * 14 * 14 * 18];   // (b, h, w, c)
__device__ float g_w2t  [288 * 64];              // [k=kk*32+ci][o]
__device__ float g_p2   [BMAX * 64 * 7 * 7];     // (b, c, h, w)

// bilinear corner sample, zero padding semantics
__device__ __forceinline__ float corner(const float* __restrict__ p,
                                        int y, int x, int H, int W, int stride) {
    bool v = (y >= 0) & (y < H) & (x >= 0) & (x < W);
    int yc = min(max(y, 0), H - 1);
    int xc = min(max(x, 0), W - 1);
    return v ? p[(yc * W + xc) * stride] : 0.f;
}

// ---------------------------------------------------------------------------
// Kernel 1: fused offset-conv(1->18) + deform-conv(1->32) + relu + maxpool2.
// ---------------------------------------------------------------------------
__global__ void __launch_bounds__(128)
k_stage1(const float* __restrict__ x,
         const float* __restrict__ ow, const float* __restrict__ ob,
         const float* __restrict__ w1, const float* __restrict__ b1, int B) {
    int idx = blockIdx.x * blockDim.x + threadIdx.x;
    if (idx >= B * 14 * 14) return;
    int w2i = idx % 14;
    int t   = idx / 14;
    int h2i = t % 14;
    int b   = t / 14;
    const float* xb = x + b * 784;

    float xp[4][9];
#pragma unroll
    for (int p = 0; p < 4; p++) {
        int h = h2i * 2 + (p >> 1), w = w2i * 2 + (p & 1);
#pragma unroll
        for (int tt = 0; tt < 9; tt++) {
            int yy = h + tt / 3 - 1, xx = w + tt % 3 - 1;
            xp[p][tt] = (yy >= 0 && yy < 28 && xx >= 0 && xx < 28) ? xb[yy * 28 + xx] : 0.f;
        }
    }

    float samp[4][9];
#pragma unroll
    for (int kk = 0; kk < 9; kk++) {
        float wr0[9], wr1[9];
#pragma unroll
        for (int tt = 0; tt < 9; tt++) {
            wr0[tt] = ow[(2 * kk) * 9 + tt];
            wr1[tt] = ow[(2 * kk + 1) * 9 + tt];
        }
        float bdy = ob[2 * kk], bdx = ob[2 * kk + 1];
        int iy = kk / 3 - 1, ix = kk % 3 - 1;
#pragma unroll
        for (int p = 0; p < 4; p++) {
            float dy = bdy, dx = bdx;
#pragma unroll
            for (int tt = 0; tt < 9; tt++) {
                dy = fmaf(wr0[tt], xp[p][tt], dy);
                dx = fmaf(wr1[tt], xp[p][tt], dx);
            }
            int h = h2i * 2 + (p >> 1), w = w2i * 2 + (p & 1);
            float py = (float)(h + iy) + dy;
            float px = (float)(w + ix) + dx;
            float fy = floorf(py), fx = floorf(px);
            float ay = py - fy, ax = px - fx;
            int y0 = (int)fy, x0 = (int)fx;
            float v00 = corner(xb, y0,     x0,     28, 28, 1);
            float v01 = corner(xb, y0,     x0 + 1, 28, 28, 1);
            float v10 = corner(xb, y0 + 1, x0,     28, 28, 1);
            float v11 = corner(xb, y0 + 1, x0 + 1, 28, 28, 1);
            samp[p][kk] = (1.f - ay) * ((1.f - ax) * v00 + ax * v01)
                        +         ay * ((1.f - ax) * v10 + ax * v11);
        }
    }

    float* o = g_p1t + (b * 196 + h2i * 14 + w2i) * 32;
#pragma unroll
    for (int oc = 0; oc < 32; oc++) {
        float wv[9];
#pragma unroll
        for (int kk = 0; kk < 9; kk++) wv[kk] = w1[oc * 9 + kk];
        float m = -1e30f;
#pragma unroll
        for (int p = 0; p < 4; p++) {
            float a = b1[oc];
#pragma unroll
            for (int kk = 0; kk < 9; kk++) a = fmaf(wv[kk], samp[p][kk], a);
            m = fmaxf(m, a);
        }
        o[oc] = fmaxf(m, 0.f);
    }
}

// ---------------------------------------------------------------------------
// Kernel 2: offset conv 2 (32 -> 18 channels, 14x14, pad 1).
// ---------------------------------------------------------------------------
__global__ void __launch_bounds__(128)
k_offconv2(const float* __restrict__ ow, const float* __restrict__ ob, int B) {
    int idx = blockIdx.x * blockDim.x + threadIdx.x;
    if (idx >= B * 14 * 7) return;
    int wp = idx % 7;
    int t  = idx / 7;
    int h  = t % 14;
    int b  = t / 14;
    int w0 = wp * 2;

    float acc[2][18];
#pragma unroll
    for (int c = 0; c < 18; c++) { acc[0][c] = ob[c]; acc[1][c] = ob[c]; }

    const float* pb = g_p1t + b * 196 * 32;

    for (int tt = 0; tt < 9; tt++) {
        int y  = h + tt / 3 - 1;
        int dx = tt % 3 - 1;
        int x0 = w0 + dx, x1 = w0 + 1 + dx;
        bool yok = (y >= 0) & (y < 14);
        bool ok0 = yok & (x0 >= 0) & (x0 < 14);
        bool ok1 = yok & (x1 >= 0) & (x1 < 14);
        const float* p0 = pb + (y * 14 + x0) * 32;
        const float* p1 = pb + (y * 14 + x1) * 32;

        for (int cib = 0; cib < 4; cib++) {
            float v0[8], v1[8];
            if (ok0) {
                float4 a = *(const float4*)(p0 + cib * 8);
                float4 c4 = *(const float4*)(p0 + cib * 8 + 4);
                v0[0] = a.x; v0[1] = a.y; v0[2] = a.z; v0[3] = a.w;
                v0[4] = c4.x; v0[5] = c4.y; v0[6] = c4.z; v0[7] = c4.w;
            } else {
#pragma unroll
                for (int q = 0; q < 8; q++) v0[q] = 0.f;
            }
            if (ok1) {
                float4 a = *(const float4*)(p1 + cib * 8);
                float4 c4 = *(const float4*)(p1 + cib * 8 + 4);
                v1[0] = a.x; v1[1] = a.y; v1[2] = a.z; v1[3] = a.w;
                v1[4] = c4.x; v1[5] = c4.y; v1[6] = c4.z; v1[7] = c4.w;
            } else {
#pragma unroll
                for (int q = 0; q < 8; q++) v1[q] = 0.f;
            }
#pragma unroll
            for (int c = 0; c < 18; c++) {
#pragma unroll
                for (int q = 0; q < 8; q++) {
                    float wv = ow[(c * 32 + cib * 8 + q) * 9 + tt];
                    acc[0][c] = fmaf(wv, v0[q], acc[0][c]);
                    acc[1][c] = fmaf(wv, v1[q], acc[1][c]);
                }
            }
        }
    }

    float* o = g_off2t + (b * 196 + h * 14 + w0) * 18;
#pragma unroll
    for (int c = 0; c < 18; c++) { o[c] = acc[0][c]; o[18 + c] = acc[1][c]; }
}

// ---------------------------------------------------------------------------
// Kernel 3: transpose w2 (64,32,3,3) -> [kk*32+ci][o]
// ---------------------------------------------------------------------------
__global__ void k_transpose_w2(const float* __restrict__ w2) {
    int i = blockIdx.x * blockDim.x + threadIdx.x;
    if (i >= 64 * 288) return;
    int o = i / 288, r = i % 288, ci = r / 9, kk = r % 9;
    g_w2t[(kk * 32 + ci) * 64 + o] = w2[i];
}

// ---------------------------------------------------------------------------
// Kernel 4: deform conv 2 (K=288 -> N=64) + relu + maxpool2, register-tiled.
// Block = FOUR pooled pixels (M = 16 quadrant-rows), 64 threads = 16(n)x4(m).
// Thread (tm,tn): m-fragment = pixel tm's 4 quadrants (contiguous in smem),
//                 n-fragment = channels tn*4..tn*4+3.
// Inner loop per k: 1 LDG.128 (weights, warp-contiguous 256B)
//                 + 2 LDS.64  (samples, 2 distinct 16B per warp, broadcast)
//                 + 16 FMA.
// LSU wavefronts per FMA ~0.3 (vs ~1.25 before) -> FMA-pipe bound.
// ---------------------------------------------------------------------------
#define SROW 18                         // floats per samp row (pad: 2-way STS max)
__global__ void __launch_bounds__(64)
k_deform2(const float* __restrict__ b2, int B) {
    __shared__ float samp[288 * SROW];  // 20736 B
    int tid  = threadIdx.x;
    int pix0 = blockIdx.x * 4;
    int npix = B * 49;

    // ---- phase 1: 16 m-rows * 288 k = 4608 bilinear samples ----
#pragma unroll 2
    for (int i = 0; i < 72; i++) {
        int e  = i * 64 + tid;
        int ci = e & 31;                 // lane -> coalesced gathers
        int u  = e >> 5;                 // 0..143, warp-uniform
        int kk = u % 9;
        int m  = u / 9;                  // 0..15:  m = pl*4 + quad
        int pl = m >> 2;
        int q  = m & 3;
        int pix = pix0 + pl;
        float val = 0.f;
        if (pix < npix) {
            int b  = pix / 49;
            int s  = pix - b * 49;
            int h3 = s / 7, w3 = s - h3 * 7;
            int h  = h3 * 2 + (q >> 1), w = w3 * 2 + (q & 1);
            const float* od = g_off2t + (b * 196 + h * 14 + w) * 18 + 2 * kk;
            float dy = od[0], dx = od[1];
            int iy = kk / 3;
            float py = (float)(h + iy - 1) + dy;
            float px = (float)(w + (kk - iy * 3) - 1) + dx;
            float fy = floorf(py), fx = floorf(px);
            float ay = py - fy, ax = px - fx;
            int y0 = (int)fy, x0 = (int)fx;
            const float* pc = g_p1t + b * 6272 + ci;
            float v00 = corner(pc, y0,     x0,     14, 14, 32);
            float v01 = corner(pc, y0,     x0 + 1, 14, 14, 32);
            float v10 = corner(pc, y0 + 1, x0,     14, 14, 32);
            float v11 = corner(pc, y0 + 1, x0 + 1, 14, 14, 32);
            val = (1.f - ay) * ((1.f - ax) * v00 + ax * v01)
                +         ay * ((1.f - ax) * v10 + ax * v11);
        }
        samp[(kk * 32 + ci) * SROW + m] = val;
    }
    __syncthreads();

    // ---- phase 2: 16x64x288 GEMM, 4(m quadrants) x 4(n) per thread ----
    int tn = tid & 15, tm = tid >> 4;
    float acc[4][4];
#pragma unroll
    for (int q = 0; q < 4; q++)
#pragma unroll
        for (int j = 0; j < 4; j++) acc[q][j] = 0.f;

    const float* wp = g_w2t + tn * 4;
    const float* sp = samp + tm * 4;

#pragma unroll 4
    for (int k = 0; k < 288; k++) {
        float4 wv = *(const float4*)(wp + k * 64);        // LDG.128, L2-hot
        float2 sa = *(const float2*)(sp + k * SROW);      // LDS.64
        float2 sb = *(const float2*)(sp + k * SROW + 2);  // LDS.64
        float s0 = sa.x, s1 = sa.y, s2 = sb.x, s3 = sb.y;
        acc[0][0] = fmaf(wv.x, s0, acc[0][0]);
        acc[0][1] = fmaf(wv.y, s0, acc[0][1]);
        acc[0][2] = fmaf(wv.z, s0, acc[0][2]);
        acc[0][3] = fmaf(wv.w, s0, acc[0][3]);
        acc[1][0] = fmaf(wv.x, s1, acc[1][0]);
        acc[1][1] = fmaf(wv.y, s1, acc[1][1]);
        acc[1][2] = fmaf(wv.z, s1, acc[1][2]);
        acc[1][3] = fmaf(wv.w, s1, acc[1][3]);
        acc[2][0] = fmaf(wv.x, s2, acc[2][0]);
        acc[2][1] = fmaf(wv.y, s2, acc[2][1]);
        acc[2][2] = fmaf(wv.z, s2, acc[2][2]);
        acc[2][3] = fmaf(wv.w, s2, acc[2][3]);
        acc[3][0] = fmaf(wv.x, s3, acc[3][0]);
        acc[3][1] = fmaf(wv.y, s3, acc[3][1]);
        acc[3][2] = fmaf(wv.z, s3, acc[3][2]);
        acc[3][3] = fmaf(wv.w, s3, acc[3][3]);
    }

    // ---- epilogue: pool(max of 4 quadrants) + bias + relu ----
    int pix = pix0 + tm;
    if (pix < npix) {
        int b = pix / 49, s = pix - b * 49;
        int h3 = s / 7, w3 = s - h3 * 7;
        float* o = g_p2 + b * 3136 + h3 * 7 + w3;
#pragma unroll
        for (int j = 0; j < 4; j++) {
            int n = tn * 4 + j;
            float m = fmaxf(fmaxf(acc[0][j], acc[1][j]), fmaxf(acc[2][j], acc[3][j]));
            o[n * 49] = fmaxf(m + b2[n], 0.f);
        }
    }
}

// ---------------------------------------------------------------------------
// Kernel 5: FC (B,3136) @ (10,3136)^T + bias. One warp per (b, oc), unrolled.
// ---------------------------------------------------------------------------
__global__ void __launch_bounds__(320)
k_fc(const float* __restrict__ fw, const float* __restrict__ fb,
     float* __restrict__ out, int B) {
    int b = blockIdx.x;
    int warp = threadIdx.x >> 5;
    int lane = threadIdx.x & 31;
    const float* row = g_p2 + b * 3136;
    const float* wr  = fw + warp * 3136;
    float s = 0.f;
    int i = lane * 4;
#pragma unroll 4
    for (int it = 0; it < 24; it++, i += 128) {
        float4 a = *(const float4*)(row + i);
        float4 w = *(const float4*)(wr + i);
        s = fmaf(a.x, w.x, s); s = fmaf(a.y, w.y, s);
        s = fmaf(a.z, w.z, s); s = fmaf(a.w, w.w, s);
    }
    if (i < 3136) {                      // tail: lanes 0..15
        float4 a = *(const float4*)(row + i);
        float4 w = *(const float4*)(wr + i);
        s = fmaf(a.x, w.x, s); s = fmaf(a.y, w.y, s);
        s = fmaf(a.z, w.z, s); s = fmaf(a.w, w.w, s);
    }
#pragma unroll
    for (int off = 16; off; off >>= 1) s += __shfl_xor_sync(0xffffffffu, s, off);
    if (lane == 0) out[b * 10 + warp] = s + fb[warp];
}

// ---------------------------------------------------------------------------
extern "C" void kernel_launch(void* const* d_in, const int* in_sizes, int n_in,
                              void* d_out, int out_size) {
    const float* x      = (const float*)d_in[0];
    const float* off_w1 = (const float*)d_in[1];
    const float* off_b1 = (const float*)d_in[2];
    const float* w1     = (const float*)d_in[3];
    const float* b1     = (const float*)d_in[4];
    const float* off_w2 = (const float*)d_in[5];
    const float* off_b2 = (const float*)d_in[6];
    const float* w2     = (const float*)d_in[7];
    const float* b2     = (const float*)d_in[8];
    const float* fc_w   = (const float*)d_in[9];
    const float* fc_b   = (const float*)d_in[10];
    float* out = (float*)d_out;

    int B = in_sizes[0] / 784;
    if (B > BMAX) B = BMAX;

    k_transpose_w2<<<(64 * 288 + 255) / 256, 256>>>(w2);
    k_stage1<<<(B * 196 + 127) / 128, 128>>>(x, off_w1, off_b1, w1, b1, B);
    k_offconv2<<<(B * 98 + 127) / 128, 128>>>(off_w2, off_b2, B);
    k_deform2<<<(B * 49 + 3) / 4, 64>>>(b2, B);
    k_fc<<<B, 320>>>(fc_w, fc_b, out, B);
}

// round 6
// speedup vs baseline: 1.0249x; 1.0249x over previous
#include <cuda_runtime.h>
#include <cuda_bf16.h>

#define BMAX 256

// scratch (channel-last where noted)
__device__ float g_p1t  [BMAX * 14 * 14 * 32];   // (b, h, w, c)
__device__ float g_off2t[BMAX * 14 * 14 * 18];   // (b, h, w, c)
__device__ float g_w2t  [288 * 64];              // [k=kk*32+ci][o]
__device__ float g_p2   [BMAX * 64 * 7 * 7];     // (b, c, h, w)

// bilinear corner sample, zero padding semantics
__device__ __forceinline__ float corner(const float* __restrict__ p,
                                        int y, int x, int H, int W, int stride) {
    bool v = (y >= 0) & (y < H) & (x >= 0) & (x < W);
    int yc = min(max(y, 0), H - 1);
    int xc = min(max(x, 0), W - 1);
    return v ? p[(yc * W + xc) * stride] : 0.f;
}

// ---------------------------------------------------------------------------
// Kernel 1: fused offset-conv(1->18) + deform-conv(1->32) + relu + maxpool2.
// ---------------------------------------------------------------------------
__global__ void __launch_bounds__(128)
k_stage1(const float* __restrict__ x,
         const float* __restrict__ ow, const float* __restrict__ ob,
         const float* __restrict__ w1, const float* __restrict__ b1, int B) {
    int idx = blockIdx.x * blockDim.x + threadIdx.x;
    if (idx >= B * 14 * 14) return;
    int w2i = idx % 14;
    int t   = idx / 14;
    int h2i = t % 14;
    int b   = t / 14;
    const float* xb = x + b * 784;

    float xp[4][9];
#pragma unroll
    for (int p = 0; p < 4; p++) {
        int h = h2i * 2 + (p >> 1), w = w2i * 2 + (p & 1);
#pragma unroll
        for (int tt = 0; tt < 9; tt++) {
            int yy = h + tt / 3 - 1, xx = w + tt % 3 - 1;
            xp[p][tt] = (yy >= 0 && yy < 28 && xx >= 0 && xx < 28) ? xb[yy * 28 + xx] : 0.f;
        }
    }

    float samp[4][9];
#pragma unroll
    for (int kk = 0; kk < 9; kk++) {
        float wr0[9], wr1[9];
#pragma unroll
        for (int tt = 0; tt < 9; tt++) {
            wr0[tt] = ow[(2 * kk) * 9 + tt];
            wr1[tt] = ow[(2 * kk + 1) * 9 + tt];
        }
        float bdy = ob[2 * kk], bdx = ob[2 * kk + 1];
        int iy = kk / 3 - 1, ix = kk % 3 - 1;
#pragma unroll
        for (int p = 0; p < 4; p++) {
            float dy = bdy, dx = bdx;
#pragma unroll
            for (int tt = 0; tt < 9; tt++) {
                dy = fmaf(wr0[tt], xp[p][tt], dy);
                dx = fmaf(wr1[tt], xp[p][tt], dx);
            }
            int h = h2i * 2 + (p >> 1), w = w2i * 2 + (p & 1);
            float py = (float)(h + iy) + dy;
            float px = (float)(w + ix) + dx;
            float fy = floorf(py), fx = floorf(px);
            float ay = py - fy, ax = px - fx;
            int y0 = (int)fy, x0 = (int)fx;
            float v00 = corner(xb, y0,     x0,     28, 28, 1);
            float v01 = corner(xb, y0,     x0 + 1, 28, 28, 1);
            float v10 = corner(xb, y0 + 1, x0,     28, 28, 1);
            float v11 = corner(xb, y0 + 1, x0 + 1, 28, 28, 1);
            samp[p][kk] = (1.f - ay) * ((1.f - ax) * v00 + ax * v01)
                        +         ay * ((1.f - ax) * v10 + ax * v11);
        }
    }

    float* o = g_p1t + (b * 196 + h2i * 14 + w2i) * 32;
#pragma unroll
    for (int oc = 0; oc < 32; oc++) {
        float wv[9];
#pragma unroll
        for (int kk = 0; kk < 9; kk++) wv[kk] = w1[oc * 9 + kk];
        float m = -1e30f;
#pragma unroll
        for (int p = 0; p < 4; p++) {
            float a = b1[oc];
#pragma unroll
            for (int kk = 0; kk < 9; kk++) a = fmaf(wv[kk], samp[p][kk], a);
            m = fmaxf(m, a);
        }
        o[oc] = fmaxf(m, 0.f);
    }
}

// ---------------------------------------------------------------------------
// Kernel 2: offset conv 2 (32 -> 18 channels, 14x14, pad 1).
// ---------------------------------------------------------------------------
__global__ void __launch_bounds__(128)
k_offconv2(const float* __restrict__ ow, const float* __restrict__ ob, int B) {
    int idx = blockIdx.x * blockDim.x + threadIdx.x;
    if (idx >= B * 14 * 7) return;
    int wp = idx % 7;
    int t  = idx / 7;
    int h  = t % 14;
    int b  = t / 14;
    int w0 = wp * 2;

    float acc[2][18];
#pragma unroll
    for (int c = 0; c < 18; c++) { acc[0][c] = ob[c]; acc[1][c] = ob[c]; }

    const float* pb = g_p1t + b * 196 * 32;

    for (int tt = 0; tt < 9; tt++) {
        int y  = h + tt / 3 - 1;
        int dx = tt % 3 - 1;
        int x0 = w0 + dx, x1 = w0 + 1 + dx;
        bool yok = (y >= 0) & (y < 14);
        bool ok0 = yok & (x0 >= 0) & (x0 < 14);
        bool ok1 = yok & (x1 >= 0) & (x1 < 14);
        const float* p0 = pb + (y * 14 + x0) * 32;
        const float* p1 = pb + (y * 14 + x1) * 32;

        for (int cib = 0; cib < 4; cib++) {
            float v0[8], v1[8];
            if (ok0) {
                float4 a = *(const float4*)(p0 + cib * 8);
                float4 c4 = *(const float4*)(p0 + cib * 8 + 4);
                v0[0] = a.x; v0[1] = a.y; v0[2] = a.z; v0[3] = a.w;
                v0[4] = c4.x; v0[5] = c4.y; v0[6] = c4.z; v0[7] = c4.w;
            } else {
#pragma unroll
                for (int q = 0; q < 8; q++) v0[q] = 0.f;
            }
            if (ok1) {
                float4 a = *(const float4*)(p1 + cib * 8);
                float4 c4 = *(const float4*)(p1 + cib * 8 + 4);
                v1[0] = a.x; v1[1] = a.y; v1[2] = a.z; v1[3] = a.w;
                v1[4] = c4.x; v1[5] = c4.y; v1[6] = c4.z; v1[7] = c4.w;
            } else {
#pragma unroll
                for (int q = 0; q < 8; q++) v1[q] = 0.f;
            }
#pragma unroll
            for (int c = 0; c < 18; c++) {
#pragma unroll
                for (int q = 0; q < 8; q++) {
                    float wv = ow[(c * 32 + cib * 8 + q) * 9 + tt];
                    acc[0][c] = fmaf(wv, v0[q], acc[0][c]);
                    acc[1][c] = fmaf(wv, v1[q], acc[1][c]);
                }
            }
        }
    }

    float* o = g_off2t + (b * 196 + h * 14 + w0) * 18;
#pragma unroll
    for (int c = 0; c < 18; c++) { o[c] = acc[0][c]; o[18 + c] = acc[1][c]; }
}

// ---------------------------------------------------------------------------
// Kernel 3: transpose w2 (64,32,3,3) -> [kk*32+ci][o]
// ---------------------------------------------------------------------------
__global__ void k_transpose_w2(const float* __restrict__ w2) {
    int i = blockIdx.x * blockDim.x + threadIdx.x;
    if (i >= 64 * 288) return;
    int o = i / 288, r = i % 288, ci = r / 9, kk = r % 9;
    g_w2t[(kk * 32 + ci) * 64 + o] = w2[i];
}

// ---------------------------------------------------------------------------
// Kernel 4: deform conv 2 (K=288 -> N=64) + relu + maxpool2.
// Block = 8 pooled pixels (M=32 quadrant rows), 128 threads = 16(n) x 8(m).
// K is processed in 3 chunks of 96 rows, ping-ponged through one 13.8 KB
// smem buffer -> ~50-60% occupancy (vs 26% with full-K staging).
// Thread (tm,tn): m-frag = pixel tm's 4 quadrants (one aligned LDS.128),
//                 n-frag = channels tn*4..+3 (one LDG.128, L1-resident).
// Inner loop per k: 1 LDG.128 + 1 LDS.128 + 16 FMA.
// ---------------------------------------------------------------------------
#define CHUNK 96                        // 3 kk-groups of 32 channels
#define SROW2 36                        // floats per k-row (32 m + pad, 16B-mult)
__global__ void __launch_bounds__(128)
k_deform2(const float* __restrict__ b2, int B) {
    __shared__ float samp[CHUNK * SROW2];     // 13824 B
    int tid  = threadIdx.x;
    int pix0 = blockIdx.x * 8;
    int npix = B * 49;
    int tn = tid & 15, tm = tid >> 4;         // tm 0..7 = pixel index

    float acc[4][4];
#pragma unroll
    for (int q = 0; q < 4; q++)
#pragma unroll
        for (int j = 0; j < 4; j++) acc[q][j] = 0.f;

    const float* wp = g_w2t + tn * 4;
    const float* sp = samp + tm * 4;

    for (int c = 0; c < 3; c++) {
        if (c) __syncthreads();               // protect smem reuse

        // ---- phase 1: 96 k-rows x 32 m = 3072 samples, 24 iters ----
#pragma unroll 2
        for (int i = 0; i < 24; i++) {
            int e  = i * 128 + tid;           // 0..3071
            int ci = e & 31;                  // lane -> coalesced gathers
            int u  = e >> 5;                  // 0..95, warp-uniform
            int kl = u % 3;                   // chunk-local kk
            int m  = u / 3;                   // 0..31
            int kk = c * 3 + kl;
            int pl = m >> 2, q = m & 3;
            int pix = pix0 + pl;
            float val = 0.f;
            if (pix < npix) {
                int b  = pix / 49;
                int s  = pix - b * 49;
                int h3 = s / 7, w3 = s - h3 * 7;
                int h  = h3 * 2 + (q >> 1), w = w3 * 2 + (q & 1);
                const float* od = g_off2t + (b * 196 + h * 14 + w) * 18 + 2 * kk;
                float dy = od[0], dx = od[1];
                int iy = kk / 3;
                float py = (float)(h + iy - 1) + dy;
                float px = (float)(w + (kk - iy * 3) - 1) + dx;
                float fy = floorf(py), fx = floorf(px);
                float ay = py - fy, ax = px - fx;
                int y0 = (int)fy, x0 = (int)fx;
                const float* pc = g_p1t + b * 6272 + ci;
                float v00 = corner(pc, y0,     x0,     14, 14, 32);
                float v01 = corner(pc, y0,     x0 + 1, 14, 14, 32);
                float v10 = corner(pc, y0 + 1, x0,     14, 14, 32);
                float v11 = corner(pc, y0 + 1, x0 + 1, 14, 14, 32);
                val = (1.f - ay) * ((1.f - ax) * v00 + ax * v01)
                    +         ay * ((1.f - ax) * v10 + ax * v11);
            }
            samp[(kl * 32 + ci) * SROW2 + m] = val;
        }
        __syncthreads();

        // ---- phase 2: 96-k GEMM slice, 4m x 4n per thread ----
        const float* wc = wp + c * CHUNK * 64;
#pragma unroll 8
        for (int k = 0; k < CHUNK; k++) {
            float4 wv = *(const float4*)(wc + k * 64);      // LDG.128, L1-hot
            float4 sv = *(const float4*)(sp + k * SROW2);   // LDS.128, aligned
            acc[0][0] = fmaf(wv.x, sv.x, acc[0][0]);
            acc[0][1] = fmaf(wv.y, sv.x, acc[0][1]);
            acc[0][2] = fmaf(wv.z, sv.x, acc[0][2]);
            acc[0][3] = fmaf(wv.w, sv.x, acc[0][3]);
            acc[1][0] = fmaf(wv.x, sv.y, acc[1][0]);
            acc[1][1] = fmaf(wv.y, sv.y, acc[1][1]);
            acc[1][2] = fmaf(wv.z, sv.y, acc[1][2]);
            acc[1][3] = fmaf(wv.w, sv.y, acc[1][3]);
            acc[2][0] = fmaf(wv.x, sv.z, acc[2][0]);
            acc[2][1] = fmaf(wv.y, sv.z, acc[2][1]);
            acc[2][2] = fmaf(wv.z, sv.z, acc[2][2]);
            acc[2][3] = fmaf(wv.w, sv.z, acc[2][3]);
            acc[3][0] = fmaf(wv.x, sv.w, acc[3][0]);
            acc[3][1] = fmaf(wv.y, sv.w, acc[3][1]);
            acc[3][2] = fmaf(wv.z, sv.w, acc[3][2]);
            acc[3][3] = fmaf(wv.w, sv.w, acc[3][3]);
        }
    }

    // ---- epilogue: pool(max of 4 quadrants) + bias + relu ----
    int pix = pix0 + tm;
    if (pix < npix) {
        int b = pix / 49, s = pix - b * 49;
        int h3 = s / 7, w3 = s - h3 * 7;
        float* o = g_p2 + b * 3136 + h3 * 7 + w3;
#pragma unroll
        for (int j = 0; j < 4; j++) {
            int n = tn * 4 + j;
            float m = fmaxf(fmaxf(acc[0][j], acc[1][j]), fmaxf(acc[2][j], acc[3][j]));
            o[n * 49] = fmaxf(m + b2[n], 0.f);
        }
    }
}

// ---------------------------------------------------------------------------
// Kernel 5: FC (B,3136) @ (10,3136)^T + bias. One warp per (b, oc), unrolled.
// ---------------------------------------------------------------------------
__global__ void __launch_bounds__(320)
k_fc(const float* __restrict__ fw, const float* __restrict__ fb,
     float* __restrict__ out, int B) {
    int b = blockIdx.x;
    int warp = threadIdx.x >> 5;
    int lane = threadIdx.x & 31;
    const float* row = g_p2 + b * 3136;
    const float* wr  = fw + warp * 3136;
    float s = 0.f;
    int i = lane * 4;
#pragma unroll 4
    for (int it = 0; it < 24; it++, i += 128) {
        float4 a = *(const float4*)(row + i);
        float4 w = *(const float4*)(wr + i);
        s = fmaf(a.x, w.x, s); s = fmaf(a.y, w.y, s);
        s = fmaf(a.z, w.z, s); s = fmaf(a.w, w.w, s);
    }
    if (i < 3136) {                      // tail: lanes 0..15
        float4 a = *(const float4*)(row + i);
        float4 w = *(const float4*)(wr + i);
        s = fmaf(a.x, w.x, s); s = fmaf(a.y, w.y, s);
        s = fmaf(a.z, w.z, s); s = fmaf(a.w, w.w, s);
    }
#pragma unroll
    for (int off = 16; off; off >>= 1) s += __shfl_xor_sync(0xffffffffu, s, off);
    if (lane == 0) out[b * 10 + warp] = s + fb[warp];
}

// ---------------------------------------------------------------------------
extern "C" void kernel_launch(void* const* d_in, const int* in_sizes, int n_in,
                              void* d_out, int out_size) {
    const float* x      = (const float*)d_in[0];
    const float* off_w1 = (const float*)d_in[1];
    const float* off_b1 = (const float*)d_in[2];
    const float* w1     = (const float*)d_in[3];
    const float* b1     = (const float*)d_in[4];
    const float* off_w2 = (const float*)d_in[5];
    const float* off_b2 = (const float*)d_in[6];
    const float* w2     = (const float*)d_in[7];
    const float* b2     = (const float*)d_in[8];
    const float* fc_w   = (const float*)d_in[9];
    const float* fc_b   = (const float*)d_in[10];
    float* out = (float*)d_out;

    int B = in_sizes[0] / 784;
    if (B > BMAX) B = BMAX;

    k_transpose_w2<<<(64 * 288 + 255) / 256, 256>>>(w2);
    k_stage1<<<(B * 196 + 127) / 128, 128>>>(x, off_w1, off_b1, w1, b1, B);
    k_offconv2<<<(B * 98 + 127) / 128, 128>>>(off_w2, off_b2, B);
    k_deform2<<<(B * 49 + 7) / 8, 128>>>(b2, B);
    k_fc<<<B, 320>>>(fc_w, fc_b, out, B);
}

// round 7
// speedup vs baseline: 1.1309x; 1.1034x over previous
#include <cuda_runtime.h>
#include <cuda_bf16.h>

#define BMAX 256

// scratch
__device__ float g_p1t [BMAX * 14 * 14 * 32];    // (b, h, w, c) channel-last
__device__ float g_w2t [288 * 64];               // [k=kk*32+ci][o]
__device__ float g_p2  [BMAX * 64 * 7 * 7];      // (b, c, h, w)
// sampling records, one per (b, h, w, kk):
//   g_recI = 4 gather offsets (batch-folded, clamped)   g_recW = 4 bilinear weights (0 if invalid corner)
__device__ int4   g_recI[BMAX * 196 * 9];
__device__ float4 g_recW[BMAX * 196 * 9];

// bilinear corner sample, zero padding semantics
__device__ __forceinline__ float corner(const float* __restrict__ p,
                                        int y, int x, int H, int W, int stride) {
    bool v = (y >= 0) & (y < H) & (x >= 0) & (x < W);
    int yc = min(max(y, 0), H - 1);
    int xc = min(max(x, 0), W - 1);
    return v ? p[(yc * W + xc) * stride] : 0.f;
}

// ---------------------------------------------------------------------------
// Kernel 1: fused offset-conv(1->18) + deform-conv(1->32) + relu + maxpool2.
// ---------------------------------------------------------------------------
__global__ void __launch_bounds__(128)
k_stage1(const float* __restrict__ x,
         const float* __restrict__ ow, const float* __restrict__ ob,
         const float* __restrict__ w1, const float* __restrict__ b1, int B) {
    int idx = blockIdx.x * blockDim.x + threadIdx.x;
    if (idx >= B * 14 * 14) return;
    int w2i = idx % 14;
    int t   = idx / 14;
    int h2i = t % 14;
    int b   = t / 14;
    const float* xb = x + b * 784;

    float xp[4][9];
#pragma unroll
    for (int p = 0; p < 4; p++) {
        int h = h2i * 2 + (p >> 1), w = w2i * 2 + (p & 1);
#pragma unroll
        for (int tt = 0; tt < 9; tt++) {
            int yy = h + tt / 3 - 1, xx = w + tt % 3 - 1;
            xp[p][tt] = (yy >= 0 && yy < 28 && xx >= 0 && xx < 28) ? xb[yy * 28 + xx] : 0.f;
        }
    }

    float samp[4][9];
#pragma unroll
    for (int kk = 0; kk < 9; kk++) {
        float wr0[9], wr1[9];
#pragma unroll
        for (int tt = 0; tt < 9; tt++) {
            wr0[tt] = ow[(2 * kk) * 9 + tt];
            wr1[tt] = ow[(2 * kk + 1) * 9 + tt];
        }
        float bdy = ob[2 * kk], bdx = ob[2 * kk + 1];
        int iy = kk / 3 - 1, ix = kk % 3 - 1;
#pragma unroll
        for (int p = 0; p < 4; p++) {
            float dy = bdy, dx = bdx;
#pragma unroll
            for (int tt = 0; tt < 9; tt++) {
                dy = fmaf(wr0[tt], xp[p][tt], dy);
                dx = fmaf(wr1[tt], xp[p][tt], dx);
            }
            int h = h2i * 2 + (p >> 1), w = w2i * 2 + (p & 1);
            float py = (float)(h + iy) + dy;
            float px = (float)(w + ix) + dx;
            float fy = floorf(py), fx = floorf(px);
            float ay = py - fy, ax = px - fx;
            int y0 = (int)fy, x0 = (int)fx;
            float v00 = corner(xb, y0,     x0,     28, 28, 1);
            float v01 = corner(xb, y0,     x0 + 1, 28, 28, 1);
            float v10 = corner(xb, y0 + 1, x0,     28, 28, 1);
            float v11 = corner(xb, y0 + 1, x0 + 1, 28, 28, 1);
            samp[p][kk] = (1.f - ay) * ((1.f - ax) * v00 + ax * v01)
                        +         ay * ((1.f - ax) * v10 + ax * v11);
        }
    }

    float* o = g_p1t + (b * 196 + h2i * 14 + w2i) * 32;
#pragma unroll
    for (int oc = 0; oc < 32; oc++) {
        float wv[9];
#pragma unroll
        for (int kk = 0; kk < 9; kk++) wv[kk] = w1[oc * 9 + kk];
        float m = -1e30f;
#pragma unroll
        for (int p = 0; p < 4; p++) {
            float a = b1[oc];
#pragma unroll
            for (int kk = 0; kk < 9; kk++) a = fmaf(wv[kk], samp[p][kk], a);
            m = fmaxf(m, a);
        }
        o[oc] = fmaxf(m, 0.f);
    }
}

// ---------------------------------------------------------------------------
// Kernel 2: offset conv 2 (32 -> 18, 14x14, pad 1) + RECORD EPILOGUE.
// Computes per-tap offsets AND emits precomputed bilinear sampling records
// (4 clamped batch-folded gather offsets + 4 masked weights) so k_deform2's
// gather phase does zero coordinate math.
// ---------------------------------------------------------------------------
__global__ void __launch_bounds__(128)
k_offconv2(const float* __restrict__ ow, const float* __restrict__ ob, int B) {
    int idx = blockIdx.x * blockDim.x + threadIdx.x;
    if (idx >= B * 14 * 7) return;
    int wp = idx % 7;
    int t  = idx / 7;
    int h  = t % 14;
    int b  = t / 14;
    int w0 = wp * 2;

    float acc[2][18];
#pragma unroll
    for (int c = 0; c < 18; c++) { acc[0][c] = ob[c]; acc[1][c] = ob[c]; }

    const float* pb = g_p1t + b * 196 * 32;

    for (int tt = 0; tt < 9; tt++) {
        int y  = h + tt / 3 - 1;
        int dx = tt % 3 - 1;
        int x0 = w0 + dx, x1 = w0 + 1 + dx;
        bool yok = (y >= 0) & (y < 14);
        bool ok0 = yok & (x0 >= 0) & (x0 < 14);
        bool ok1 = yok & (x1 >= 0) & (x1 < 14);
        const float* p0 = pb + (y * 14 + x0) * 32;
        const float* p1 = pb + (y * 14 + x1) * 32;

        for (int cib = 0; cib < 4; cib++) {
            float v0[8], v1[8];
            if (ok0) {
                float4 a = *(const float4*)(p0 + cib * 8);
                float4 c4 = *(const float4*)(p0 + cib * 8 + 4);
                v0[0] = a.x; v0[1] = a.y; v0[2] = a.z; v0[3] = a.w;
                v0[4] = c4.x; v0[5] = c4.y; v0[6] = c4.z; v0[7] = c4.w;
            } else {
#pragma unroll
                for (int q = 0; q < 8; q++) v0[q] = 0.f;
            }
            if (ok1) {
                float4 a = *(const float4*)(p1 + cib * 8);
                float4 c4 = *(const float4*)(p1 + cib * 8 + 4);
                v1[0] = a.x; v1[1] = a.y; v1[2] = a.z; v1[3] = a.w;
                v1[4] = c4.x; v1[5] = c4.y; v1[6] = c4.z; v1[7] = c4.w;
            } else {
#pragma unroll
                for (int q = 0; q < 8; q++) v1[q] = 0.f;
            }
#pragma unroll
            for (int c = 0; c < 18; c++) {
#pragma unroll
                for (int q = 0; q < 8; q++) {
                    float wv = ow[(c * 32 + cib * 8 + q) * 9 + tt];
                    acc[0][c] = fmaf(wv, v0[q], acc[0][c]);
                    acc[1][c] = fmaf(wv, v1[q], acc[1][c]);
                }
            }
        }
    }

    // ---- record epilogue: 2 pixels x 9 taps ----
    int bbase = b * 6272;                       // batch fold into offsets
#pragma unroll
    for (int pix = 0; pix < 2; pix++) {
        int w  = w0 + pix;
        int ri = (b * 196 + h * 14 + w) * 9;
#pragma unroll
        for (int kk = 0; kk < 9; kk++) {
            float dy = acc[pix][2 * kk], dx = acc[pix][2 * kk + 1];
            float py = (float)(h + kk / 3 - 1) + dy;
            float px = (float)(w + kk % 3 - 1) + dx;
            float fy = floorf(py), fx = floorf(px);
            float ay = py - fy, ax = px - fx;
            int y0 = (int)fy, x0i = (int)fx;
            int y1 = y0 + 1,  x1i = x0i + 1;
            float vy0 = (y0  >= 0 && y0  < 14) ? 1.f : 0.f;
            float vy1 = (y1  >= 0 && y1  < 14) ? 1.f : 0.f;
            float vx0 = (x0i >= 0 && x0i < 14) ? 1.f : 0.f;
            float vx1 = (x1i >= 0 && x1i < 14) ? 1.f : 0.f;
            int yc0 = min(max(y0, 0), 13),  yc1 = min(max(y1, 0), 13);
            int xc0 = min(max(x0i, 0), 13), xc1 = min(max(x1i, 0), 13);
            g_recI[ri + kk] = make_int4(bbase + (yc0 * 14 + xc0) * 32,
                                        bbase + (yc0 * 14 + xc1) * 32,
                                        bbase + (yc1 * 14 + xc0) * 32,
                                        bbase + (yc1 * 14 + xc1) * 32);
            g_recW[ri + kk] = make_float4((1.f - ay) * (1.f - ax) * vy0 * vx0,
                                          (1.f - ay) * ax         * vy0 * vx1,
                                          ay * (1.f - ax)         * vy1 * vx0,
                                          ay * ax                 * vy1 * vx1);
        }
    }
}

// ---------------------------------------------------------------------------
// Kernel 3: transpose w2 (64,32,3,3) -> [kk*32+ci][o]
// ---------------------------------------------------------------------------
__global__ void k_transpose_w2(const float* __restrict__ w2) {
    int i = blockIdx.x * blockDim.x + threadIdx.x;
    if (i >= 64 * 288) return;
    int o = i / 288, r = i % 288, ci = r / 9, kk = r % 9;
    g_w2t[(kk * 32 + ci) * 64 + o] = w2[i];
}

// ---------------------------------------------------------------------------
// Kernel 4: deform conv 2 (K=288 -> N=64) + relu + maxpool2.
// Block = 8 pooled pixels (M=32 quadrant rows), 128 threads = 16(n) x 8(m).
// K in 3 chunks of 96 rows through one 13.8 KB smem buffer.
// Phase 1 (gather) now uses precomputed records: per warp-iter
//   2 broadcast LDG.128 (record) + 4 coalesced gathers + 4 FMA, no coord math.
// Phase 2 per k: 1 LDG.128 (weights) + 1 LDS.128 (samples) + 16 FMA.
// ---------------------------------------------------------------------------
#define CHUNK 96
#define SROW2 36
__global__ void __launch_bounds__(128)
k_deform2(const float* __restrict__ b2, int B) {
    __shared__ float samp[CHUNK * SROW2];     // 13824 B
    __shared__ int   recbase[32];             // record base per m-row
    int tid  = threadIdx.x;
    int pix0 = blockIdx.x * 8;
    int npix = B * 49;
    int tn = tid & 15, tm = tid >> 4;
    int wid = tid >> 5, lane = tid & 31;

    if (tid < 32) {
        int m = tid, pl = m >> 2, q = m & 3;
        int pix = pix0 + pl;
        int rb = -1;
        if (pix < npix) {
            int b  = pix / 49;
            int s  = pix - b * 49;
            int h3 = s / 7, w3 = s - h3 * 7;
            int h  = h3 * 2 + (q >> 1), w = w3 * 2 + (q & 1);
            rb = (b * 196 + h * 14 + w) * 9;
        }
        recbase[m] = rb;
    }

    float acc[4][4];
#pragma unroll
    for (int q = 0; q < 4; q++)
#pragma unroll
        for (int j = 0; j < 4; j++) acc[q][j] = 0.f;

    const float* wp = g_w2t + tn * 4;
    const float* sp = samp + tm * 4;

    for (int c = 0; c < 3; c++) {
        __syncthreads();                      // recbase ready / smem reuse

        // ---- phase 1: 96 k-rows x 32 m, no coordinate math ----
#pragma unroll 4
        for (int i = 0; i < 24; i++) {
            int u  = i * 4 + wid;             // 0..95
            int kl = u >> 5;                  // chunk-local kk (0..2)
            int m  = u & 31;                  // m-row
            int rb = recbase[m];
            float val = 0.f;
            if (rb >= 0) {
                int r = rb + c * 3 + kl;
                int4   o  = g_recI[r];        // broadcast LDG.128
                float4 wv = g_recW[r];        // broadcast LDG.128
                val = wv.x * g_p1t[o.x + lane]
                    + wv.y * g_p1t[o.y + lane]
                    + wv.z * g_p1t[o.z + lane]
                    + wv.w * g_p1t[o.w + lane];
            }
            samp[(kl * 32 + lane) * SROW2 + m] = val;
        }
        __syncthreads();

        // ---- phase 2: 96-k GEMM slice, 4m x 4n per thread ----
        const float* wc = wp + c * CHUNK * 64;
#pragma unroll 8
        for (int k = 0; k < CHUNK; k++) {
            float4 wv = *(const float4*)(wc + k * 64);      // LDG.128, L1-hot
            float4 sv = *(const float4*)(sp + k * SROW2);   // LDS.128, aligned
            acc[0][0] = fmaf(wv.x, sv.x, acc[0][0]);
            acc[0][1] = fmaf(wv.y, sv.x, acc[0][1]);
            acc[0][2] = fmaf(wv.z, sv.x, acc[0][2]);
            acc[0][3] = fmaf(wv.w, sv.x, acc[0][3]);
            acc[1][0] = fmaf(wv.x, sv.y, acc[1][0]);
            acc[1][1] = fmaf(wv.y, sv.y, acc[1][1]);
            acc[1][2] = fmaf(wv.z, sv.y, acc[1][2]);
            acc[1][3] = fmaf(wv.w, sv.y, acc[1][3]);
            acc[2][0] = fmaf(wv.x, sv.z, acc[2][0]);
            acc[2][1] = fmaf(wv.y, sv.z, acc[2][1]);
            acc[2][2] = fmaf(wv.z, sv.z, acc[2][2]);
            acc[2][3] = fmaf(wv.w, sv.z, acc[2][3]);
            acc[3][0] = fmaf(wv.x, sv.w, acc[3][0]);
            acc[3][1] = fmaf(wv.y, sv.w, acc[3][1]);
            acc[3][2] = fmaf(wv.z, sv.w, acc[3][2]);
            acc[3][3] = fmaf(wv.w, sv.w, acc[3][3]);
        }
    }

    // ---- epilogue: pool(max of 4 quadrants) + bias + relu ----
    int pix = pix0 + tm;
    if (pix < npix) {
        int b = pix / 49, s = pix - b * 49;
        int h3 = s / 7, w3 = s - h3 * 7;
        float* o = g_p2 + b * 3136 + h3 * 7 + w3;
#pragma unroll
        for (int j = 0; j < 4; j++) {
            int n = tn * 4 + j;
            float m = fmaxf(fmaxf(acc[0][j], acc[1][j]), fmaxf(acc[2][j], acc[3][j]));
            o[n * 49] = fmaxf(m + b2[n], 0.f);
        }
    }
}

// ---------------------------------------------------------------------------
// Kernel 5: FC (B,3136) @ (10,3136)^T + bias. One warp per (b, oc), unrolled.
// ---------------------------------------------------------------------------
__global__ void __launch_bounds__(320)
k_fc(const float* __restrict__ fw, const float* __restrict__ fb,
     float* __restrict__ out, int B) {
    int b = blockIdx.x;
    int warp = threadIdx.x >> 5;
    int lane = threadIdx.x & 31;
    const float* row = g_p2 + b * 3136;
    const float* wr  = fw + warp * 3136;
    float s = 0.f;
    int i = lane * 4;
#pragma unroll 4
    for (int it = 0; it < 24; it++, i += 128) {
        float4 a = *(const float4*)(row + i);
        float4 w = *(const float4*)(wr + i);
        s = fmaf(a.x, w.x, s); s = fmaf(a.y, w.y, s);
        s = fmaf(a.z, w.z, s); s = fmaf(a.w, w.w, s);
    }
    if (i < 3136) {
        float4 a = *(const float4*)(row + i);
        float4 w = *(const float4*)(wr + i);
        s = fmaf(a.x, w.x, s); s = fmaf(a.y, w.y, s);
        s = fmaf(a.z, w.z, s); s = fmaf(a.w, w.w, s);
    }
#pragma unroll
    for (int off = 16; off; off >>= 1) s += __shfl_xor_sync(0xffffffffu, s, off);
    if (lane == 0) out[b * 10 + warp] = s + fb[warp];
}

// ---------------------------------------------------------------------------
extern "C" void kernel_launch(void* const* d_in, const int* in_sizes, int n_in,
                              void* d_out, int out_size) {
    const float* x      = (const float*)d_in[0];
    const float* off_w1 = (const float*)d_in[1];
    const float* off_b1 = (const float*)d_in[2];
    const float* w1     = (const float*)d_in[3];
    const float* b1     = (const float*)d_in[4];
    const float* off_w2 = (const float*)d_in[5];
    const float* off_b2 = (const float*)d_in[6];
    const float* w2     = (const float*)d_in[7];
    const float* b2     = (const float*)d_in[8];
    const float* fc_w   = (const float*)d_in[9];
    const float* fc_b   = (const float*)d_in[10];
    float* out = (float*)d_out;

    int B = in_sizes[0] / 784;
    if (B > BMAX) B = BMAX;

    k_transpose_w2<<<(64 * 288 + 255) / 256, 256>>>(w2);
    k_stage1<<<(B * 196 + 127) / 128, 128>>>(x, off_w1, off_b1, w1, b1, B);
    k_offconv2<<<(B * 98 + 127) / 128, 128>>>(off_w2, off_b2, B);
    k_deform2<<<(B * 49 + 7) / 8, 128>>>(b2, B);
    k_fc<<<B, 320>>>(fc_w, fc_b, out, B);
}

// round 8
// speedup vs baseline: 1.2206x; 1.0793x over previous
#include <cuda_runtime.h>
#include <cuda_bf16.h>

#define BMAX 256

// scratch
__device__ float g_p1t [BMAX * 14 * 14 * 32];    // (b, h, w, c) channel-last
__device__ float g_w2t [288 * 64];               // [k=kk*32+ci][o]
__device__ float g_p2  [BMAX * 64 * 7 * 7];      // (b, c, h, w)
// sampling records, one per (b, h, w, kk):
__device__ int4   g_recI[BMAX * 196 * 9];        // 4 clamped batch-folded gather offsets
__device__ float4 g_recW[BMAX * 196 * 9];        // 4 bilinear weights (0 if invalid corner)

// bilinear corner sample, zero padding semantics
__device__ __forceinline__ float corner(const float* __restrict__ p,
                                        int y, int x, int H, int W, int stride) {
    bool v = (y >= 0) & (y < H) & (x >= 0) & (x < W);
    int yc = min(max(y, 0), H - 1);
    int xc = min(max(x, 0), W - 1);
    return v ? p[(yc * W + xc) * stride] : 0.f;
}

// ---------------------------------------------------------------------------
// Kernel 1: fused offset-conv(1->18) + deform-conv(1->32) + relu + maxpool2.
// One thread per QUADRANT (4 threads per pooled pixel, adjacent lanes);
// maxpool via shfl_xor over the quad group. 4x the warps of the old version.
// ---------------------------------------------------------------------------
__global__ void __launch_bounds__(128)
k_stage1(const float* __restrict__ x,
         const float* __restrict__ ow, const float* __restrict__ ob,
         const float* __restrict__ w1, const float* __restrict__ b1, int B) {
    int idx  = blockIdx.x * blockDim.x + threadIdx.x;
    int quad = idx & 3;
    int pix  = idx >> 2;
    int npix = B * 196;
    bool valid = pix < npix;
    if (!valid) pix = npix - 1;           // clamp: compute redundantly, no divergence
    int w2i = pix % 14;
    int t   = pix / 14;
    int h2i = t % 14;
    int b   = t / 14;
    int h = h2i * 2 + (quad >> 1), w = w2i * 2 + (quad & 1);
    const float* xb = x + b * 784;

    // 3x3 input patch for this quadrant's pixel
    float xp[9];
#pragma unroll
    for (int tt = 0; tt < 9; tt++) {
        int yy = h + tt / 3 - 1, xx = w + tt % 3 - 1;
        xp[tt] = (yy >= 0 && yy < 28 && xx >= 0 && xx < 28) ? xb[yy * 28 + xx] : 0.f;
    }

    // 9 offset taps + bilinear samples
    float samp[9];
#pragma unroll
    for (int kk = 0; kk < 9; kk++) {
        float dy = ob[2 * kk], dx = ob[2 * kk + 1];
#pragma unroll
        for (int tt = 0; tt < 9; tt++) {
            dy = fmaf(ow[(2 * kk) * 9 + tt],     xp[tt], dy);
            dx = fmaf(ow[(2 * kk + 1) * 9 + tt], xp[tt], dx);
        }
        float py = (float)(h + kk / 3 - 1) + dy;
        float px = (float)(w + kk % 3 - 1) + dx;
        float fy = floorf(py), fx = floorf(px);
        float ay = py - fy, ax = px - fx;
        int y0 = (int)fy, x0 = (int)fx;
        float v00 = corner(xb, y0,     x0,     28, 28, 1);
        float v01 = corner(xb, y0,     x0 + 1, 28, 28, 1);
        float v10 = corner(xb, y0 + 1, x0,     28, 28, 1);
        float v11 = corner(xb, y0 + 1, x0 + 1, 28, 28, 1);
        samp[kk] = (1.f - ay) * ((1.f - ax) * v00 + ax * v01)
                 +         ay * ((1.f - ax) * v10 + ax * v11);
    }

    // 32 output channels: dot + bias; pool across the 4 quad lanes; relu.
    float* o = g_p1t + pix * 32;
#pragma unroll
    for (int oc = 0; oc < 32; oc++) {
        float a = b1[oc];
#pragma unroll
        for (int kk = 0; kk < 9; kk++) a = fmaf(w1[oc * 9 + kk], samp[kk], a);
        a = fmaxf(a, __shfl_xor_sync(0xffffffffu, a, 1));
        a = fmaxf(a, __shfl_xor_sync(0xffffffffu, a, 2));
        if (quad == 0 && valid) o[oc] = fmaxf(a, 0.f);
    }
}

// ---------------------------------------------------------------------------
// Kernel 2: offset conv 2 (32 -> 18, 14x14, pad 1) + RECORD EPILOGUE.
// One thread per pixel (2x the warps of the pair version). Emits precomputed
// bilinear sampling records so k_deform2's gather phase has zero coord math.
// ---------------------------------------------------------------------------
__global__ void __launch_bounds__(128)
k_offconv2(const float* __restrict__ ow, const float* __restrict__ ob, int B) {
    int idx = blockIdx.x * blockDim.x + threadIdx.x;
    if (idx >= B * 196) return;
    int w = idx % 14;
    int t = idx / 14;
    int h = t % 14;
    int b = t / 14;

    float acc[18];
#pragma unroll
    for (int c = 0; c < 18; c++) acc[c] = ob[c];

    const float* pb = g_p1t + b * 196 * 32;

    for (int tt = 0; tt < 9; tt++) {
        int y  = h + tt / 3 - 1;
        int xx = w + tt % 3 - 1;
        bool ok = (y >= 0) & (y < 14) & (xx >= 0) & (xx < 14);
        const float* p0 = pb + (y * 14 + xx) * 32;

        for (int cib = 0; cib < 4; cib++) {
            float v[8];
            if (ok) {
                float4 a  = *(const float4*)(p0 + cib * 8);
                float4 c4 = *(const float4*)(p0 + cib * 8 + 4);
                v[0] = a.x;  v[1] = a.y;  v[2] = a.z;  v[3] = a.w;
                v[4] = c4.x; v[5] = c4.y; v[6] = c4.z; v[7] = c4.w;
            } else {
#pragma unroll
                for (int q = 0; q < 8; q++) v[q] = 0.f;
            }
#pragma unroll
            for (int c = 0; c < 18; c++) {
#pragma unroll
                for (int q = 0; q < 8; q++) {
                    acc[c] = fmaf(ow[(c * 32 + cib * 8 + q) * 9 + tt], v[q], acc[c]);
                }
            }
        }
    }

    // ---- record epilogue: 9 taps for this pixel ----
    int bbase = b * 6272;
    int ri = idx * 9;
#pragma unroll
    for (int kk = 0; kk < 9; kk++) {
        float dy = acc[2 * kk], dx = acc[2 * kk + 1];
        float py = (float)(h + kk / 3 - 1) + dy;
        float px = (float)(w + kk % 3 - 1) + dx;
        float fy = floorf(py), fx = floorf(px);
        float ay = py - fy, ax = px - fx;
        int y0 = (int)fy, x0i = (int)fx;
        int y1 = y0 + 1,  x1i = x0i + 1;
        float vy0 = (y0  >= 0 && y0  < 14) ? 1.f : 0.f;
        float vy1 = (y1  >= 0 && y1  < 14) ? 1.f : 0.f;
        float vx0 = (x0i >= 0 && x0i < 14) ? 1.f : 0.f;
        float vx1 = (x1i >= 0 && x1i < 14) ? 1.f : 0.f;
        int yc0 = min(max(y0, 0), 13),  yc1 = min(max(y1, 0), 13);
        int xc0 = min(max(x0i, 0), 13), xc1 = min(max(x1i, 0), 13);
        g_recI[ri + kk] = make_int4(bbase + (yc0 * 14 + xc0) * 32,
                                    bbase + (yc0 * 14 + xc1) * 32,
                                    bbase + (yc1 * 14 + xc0) * 32,
                                    bbase + (yc1 * 14 + xc1) * 32);
        g_recW[ri + kk] = make_float4((1.f - ay) * (1.f - ax) * vy0 * vx0,
                                      (1.f - ay) * ax         * vy0 * vx1,
                                      ay * (1.f - ax)         * vy1 * vx0,
                                      ay * ax                 * vy1 * vx1);
    }
}

// ---------------------------------------------------------------------------
// Kernel 3: transpose w2 (64,32,3,3) -> [kk*32+ci][o]
// ---------------------------------------------------------------------------
__global__ void k_transpose_w2(const float* __restrict__ w2) {
    int i = blockIdx.x * blockDim.x + threadIdx.x;
    if (i >= 64 * 288) return;
    int o = i / 288, r = i % 288, ci = r / 9, kk = r % 9;
    g_w2t[(kk * 32 + ci) * 64 + o] = w2[i];
}

// ---------------------------------------------------------------------------
// Kernel 4: deform conv 2 (K=288 -> N=64) + relu + maxpool2.
// Block = 8 pooled pixels (M=32 quadrant rows), 128 threads = 16(n) x 8(m).
// NEW: all 288 sampling records for the block are batch-prefetched into smem
// at kernel start (fully independent coalesced LDGs -> one DRAM round trip),
// so phase-1 iterations are LDS + L2 gathers only.
// ---------------------------------------------------------------------------
#define CHUNK 96
#define SROW2 36
__global__ void __launch_bounds__(128)
k_deform2(const float* __restrict__ b2, int B) {
    __shared__ float  samp[CHUNK * SROW2];    // 13824 B
    __shared__ int4   srecI[288];             // 4608 B
    __shared__ float4 srecW[288];             // 4608 B
    __shared__ int    recbase[32];
    int tid  = threadIdx.x;
    int pix0 = blockIdx.x * 8;
    int npix = B * 49;
    int tn = tid & 15, tm = tid >> 4;
    int wid = tid >> 5, lane = tid & 31;

    if (tid < 32) {
        int m = tid, pl = m >> 2, q = m & 3;
        int pix = pix0 + pl;
        int rb = -1;
        if (pix < npix) {
            int b  = pix / 49;
            int s  = pix - b * 49;
            int h3 = s / 7, w3 = s - h3 * 7;
            int h  = h3 * 2 + (q >> 1), w = w3 * 2 + (q & 1);
            rb = (b * 196 + h * 14 + w) * 9;
        }
        recbase[m] = rb;
    }
    __syncthreads();

    // ---- batch record prefetch: 288 records x 32B, all loads independent ----
    for (int t = tid; t < 288; t += 128) {
        int m = t / 9, kk = t - m * 9;
        int rb = recbase[m];
        if (rb >= 0) {
            srecI[t] = g_recI[rb + kk];
            srecW[t] = g_recW[rb + kk];
        } else {
            srecI[t] = make_int4(0, 0, 0, 0);
            srecW[t] = make_float4(0.f, 0.f, 0.f, 0.f);
        }
    }

    float acc[4][4];
#pragma unroll
    for (int q = 0; q < 4; q++)
#pragma unroll
        for (int j = 0; j < 4; j++) acc[q][j] = 0.f;

    const float* wp = g_w2t + tn * 4;
    const float* sp = samp + tm * 4;

    for (int c = 0; c < 3; c++) {
        __syncthreads();                      // srec ready / samp reuse

        // ---- phase 1: 96 k-rows x 32 m; records from smem, gathers hit L2 ----
#pragma unroll 4
        for (int i = 0; i < 24; i++) {
            int u  = i * 4 + wid;             // 0..95
            int kl = u >> 5;                  // chunk-local kk (0..2)
            int m  = u & 31;                  // m-row
            int r  = m * 9 + c * 3 + kl;
            int4   o  = srecI[r];             // broadcast LDS.128
            float4 wv = srecW[r];             // broadcast LDS.128
            float val = wv.x * g_p1t[o.x + lane]
                      + wv.y * g_p1t[o.y + lane]
                      + wv.z * g_p1t[o.z + lane]
                      + wv.w * g_p1t[o.w + lane];
            samp[(kl * 32 + lane) * SROW2 + m] = val;
        }
        __syncthreads();

        // ---- phase 2: 96-k GEMM slice, 4m x 4n per thread ----
        const float* wc = wp + c * CHUNK * 64;
#pragma unroll 8
        for (int k = 0; k < CHUNK; k++) {
            float4 wv = *(const float4*)(wc + k * 64);      // LDG.128, L1-hot
            float4 sv = *(const float4*)(sp + k * SROW2);   // LDS.128, aligned
            acc[0][0] = fmaf(wv.x, sv.x, acc[0][0]);
            acc[0][1] = fmaf(wv.y, sv.x, acc[0][1]);
            acc[0][2] = fmaf(wv.z, sv.x, acc[0][2]);
            acc[0][3] = fmaf(wv.w, sv.x, acc[0][3]);
            acc[1][0] = fmaf(wv.x, sv.y, acc[1][0]);
            acc[1][1] = fmaf(wv.y, sv.y, acc[1][1]);
            acc[1][2] = fmaf(wv.z, sv.y, acc[1][2]);
            acc[1][3] = fmaf(wv.w, sv.y, acc[1][3]);
            acc[2][0] = fmaf(wv.x, sv.z, acc[2][0]);
            acc[2][1] = fmaf(wv.y, sv.z, acc[2][1]);
            acc[2][2] = fmaf(wv.z, sv.z, acc[2][2]);
            acc[2][3] = fmaf(wv.w, sv.z, acc[2][3]);
            acc[3][0] = fmaf(wv.x, sv.w, acc[3][0]);
            acc[3][1] = fmaf(wv.y, sv.w, acc[3][1]);
            acc[3][2] = fmaf(wv.z, sv.w, acc[3][2]);
            acc[3][3] = fmaf(wv.w, sv.w, acc[3][3]);
        }
    }

    // ---- epilogue: pool(max of 4 quadrants) + bias + relu ----
    int pix = pix0 + tm;
    if (pix < npix) {
        int b = pix / 49, s = pix - b * 49;
        int h3 = s / 7, w3 = s - h3 * 7;
        float* o = g_p2 + b * 3136 + h3 * 7 + w3;
#pragma unroll
        for (int j = 0; j < 4; j++) {
            int n = tn * 4 + j;
            float m = fmaxf(fmaxf(acc[0][j], acc[1][j]), fmaxf(acc[2][j], acc[3][j]));
            o[n * 49] = fmaxf(m + b2[n], 0.f);
        }
    }
}

// ---------------------------------------------------------------------------
// Kernel 5: FC (B,3136) @ (10,3136)^T + bias. One warp per (b, oc), unrolled.
// ---------------------------------------------------------------------------
__global__ void __launch_bounds__(320)
k_fc(const float* __restrict__ fw, const float* __restrict__ fb,
     float* __restrict__ out, int B) {
    int b = blockIdx.x;
    int warp = threadIdx.x >> 5;
    int lane = threadIdx.x & 31;
    const float* row = g_p2 + b * 3136;
    const float* wr  = fw + warp * 3136;
    float s = 0.f;
    int i = lane * 4;
#pragma unroll 4
    for (int it = 0; it < 24; it++, i += 128) {
        float4 a = *(const float4*)(row + i);
        float4 w = *(const float4*)(wr + i);
        s = fmaf(a.x, w.x, s); s = fmaf(a.y, w.y, s);
        s = fmaf(a.z, w.z, s); s = fmaf(a.w, w.w, s);
    }
    if (i < 3136) {
        float4 a = *(const float4*)(row + i);
        float4 w = *(const float4*)(wr + i);
        s = fmaf(a.x, w.x, s); s = fmaf(a.y, w.y, s);
        s = fmaf(a.z, w.z, s); s = fmaf(a.w, w.w, s);
    }
#pragma unroll
    for (int off = 16; off; off >>= 1) s += __shfl_xor_sync(0xffffffffu, s, off);
    if (lane == 0) out[b * 10 + warp] = s + fb[warp];
}

// ---------------------------------------------------------------------------
extern "C" void kernel_launch(void* const* d_in, const int* in_sizes, int n_in,
                              void* d_out, int out_size) {
    const float* x      = (const float*)d_in[0];
    const float* off_w1 = (const float*)d_in[1];
    const float* off_b1 = (const float*)d_in[2];
    const float* w1     = (const float*)d_in[3];
    const float* b1     = (const float*)d_in[4];
    const float* off_w2 = (const float*)d_in[5];
    const float* off_b2 = (const float*)d_in[6];
    const float* w2     = (const float*)d_in[7];
    const float* b2     = (const float*)d_in[8];
    const float* fc_w   = (const float*)d_in[9];
    const float* fc_b   = (const float*)d_in[10];
    float* out = (float*)d_out;

    int B = in_sizes[0] / 784;
    if (B > BMAX) B = BMAX;

    k_transpose_w2<<<(64 * 288 + 255) / 256, 256>>>(w2);
    k_stage1<<<(B * 784 + 127) / 128, 128>>>(x, off_w1, off_b1, w1, b1, B);
    k_offconv2<<<(B * 196 + 127) / 128, 128>>>(off_w2, off_b2, B);
    k_deform2<<<(B * 49 + 7) / 8, 128>>>(b2, B);
    k_fc<<<B, 320>>>(fc_w, fc_b, out, B);
}

// round 9
// speedup vs baseline: 1.2859x; 1.0535x over previous
#include <cuda_runtime.h>
#include <cuda_bf16.h>

#define BMAX 256

// scratch
__device__ float g_p1t [BMAX * 14 * 14 * 32];    // (b, h, w, c) channel-last
__device__ float g_w2t [288 * 64];               // [k=kk*32+ci][o]
__device__ float g_ow2p[288 * 24];               // [k=tt*32+ci][c pad 18->24], 16B-aligned rows
__device__ float g_p2  [BMAX * 64 * 7 * 7];      // (b, c, h, w)
// sampling records, one per (b, h, w, kk):
__device__ int4   g_recI[BMAX * 196 * 9];        // 4 clamped batch-folded gather offsets
__device__ float4 g_recW[BMAX * 196 * 9];        // 4 bilinear weights (0 if invalid corner)

// bilinear corner sample, zero padding semantics
__device__ __forceinline__ float corner(const float* __restrict__ p,
                                        int y, int x, int H, int W, int stride) {
    bool v = (y >= 0) & (y < H) & (x >= 0) & (x < W);
    int yc = min(max(y, 0), H - 1);
    int xc = min(max(x, 0), W - 1);
    return v ? p[(yc * W + xc) * stride] : 0.f;
}

// ---------------------------------------------------------------------------
// Kernel 0: weight prep.
//  - w2 (64,32,3,3)      -> g_w2t [kk*32+ci][o]
//  - off_w2 (18,32,3,3)  -> g_ow2p[tt*32+ci][c], c padded to 24 with zeros
// ---------------------------------------------------------------------------
__global__ void k_prep(const float* __restrict__ w2,
                       const float* __restrict__ off_w2) {
    int i = blockIdx.x * blockDim.x + threadIdx.x;
    if (i < 64 * 288) {
        int o = i / 288, r = i % 288, ci = r / 9, kk = r % 9;
        g_w2t[(kk * 32 + ci) * 64 + o] = w2[i];
    } else {
        int j = i - 64 * 288;
        if (j < 288 * 24) {
            int k = j / 24, c = j % 24;
            int tt = k / 32, ci = k % 32;
            g_ow2p[j] = (c < 18) ? off_w2[(c * 32 + ci) * 9 + tt] : 0.f;
        }
    }
}

// ---------------------------------------------------------------------------
// Kernel 1: fused offset-conv(1->18) + deform-conv(1->32) + relu + maxpool2.
// One thread per QUADRANT; maxpool via shfl_xor. Weights staged in smem
// (scalar LDS issue floor 2cyc/SMSP vs LDG 1.82cyc/SM -> ~3.6x issue rate).
// ---------------------------------------------------------------------------
__global__ void __launch_bounds__(128)
k_stage1(const float* __restrict__ x,
         const float* __restrict__ ow, const float* __restrict__ ob,
         const float* __restrict__ w1, const float* __restrict__ b1, int B) {
    __shared__ float ows[162], w1s[288], obs[18], b1s[32];
    {
        int t = threadIdx.x;
        for (int i = t; i < 162; i += 128) ows[i] = ow[i];
        for (int i = t; i < 288; i += 128) w1s[i] = w1[i];
        if (t < 18) obs[t] = ob[t];
        if (t >= 32 && t < 64) b1s[t - 32] = b1[t - 32];
    }
    __syncthreads();

    int idx  = blockIdx.x * blockDim.x + threadIdx.x;
    int quad = idx & 3;
    int pix  = idx >> 2;
    int npix = B * 196;
    bool valid = pix < npix;
    if (!valid) pix = npix - 1;
    int w2i = pix % 14;
    int t   = pix / 14;
    int h2i = t % 14;
    int b   = t / 14;
    int h = h2i * 2 + (quad >> 1), w = w2i * 2 + (quad & 1);
    const float* xb = x + b * 784;

    float xp[9];
#pragma unroll
    for (int tt = 0; tt < 9; tt++) {
        int yy = h + tt / 3 - 1, xx = w + tt % 3 - 1;
        xp[tt] = (yy >= 0 && yy < 28 && xx >= 0 && xx < 28) ? xb[yy * 28 + xx] : 0.f;
    }

    float samp[9];
#pragma unroll
    for (int kk = 0; kk < 9; kk++) {
        float dy = obs[2 * kk], dx = obs[2 * kk + 1];
#pragma unroll
        for (int tt = 0; tt < 9; tt++) {
            dy = fmaf(ows[(2 * kk) * 9 + tt],     xp[tt], dy);
            dx = fmaf(ows[(2 * kk + 1) * 9 + tt], xp[tt], dx);
        }
        float py = (float)(h + kk / 3 - 1) + dy;
        float px = (float)(w + kk % 3 - 1) + dx;
        float fy = floorf(py), fx = floorf(px);
        float ay = py - fy, ax = px - fx;
        int y0 = (int)fy, x0 = (int)fx;
        float v00 = corner(xb, y0,     x0,     28, 28, 1);
        float v01 = corner(xb, y0,     x0 + 1, 28, 28, 1);
        float v10 = corner(xb, y0 + 1, x0,     28, 28, 1);
        float v11 = corner(xb, y0 + 1, x0 + 1, 28, 28, 1);
        samp[kk] = (1.f - ay) * ((1.f - ax) * v00 + ax * v01)
                 +         ay * ((1.f - ax) * v10 + ax * v11);
    }

    float* o = g_p1t + pix * 32;
#pragma unroll
    for (int oc = 0; oc < 32; oc++) {
        float a = b1s[oc];
#pragma unroll
        for (int kk = 0; kk < 9; kk++) a = fmaf(w1s[oc * 9 + kk], samp[kk], a);
        a = fmaxf(a, __shfl_xor_sync(0xffffffffu, a, 1));
        a = fmaxf(a, __shfl_xor_sync(0xffffffffu, a, 2));
        if (quad == 0 && valid) o[oc] = fmaxf(a, 0.f);
    }
}

// ---------------------------------------------------------------------------
// Kernel 2: offset conv 2 (32 -> 18, 14x14, pad 1) + RECORD EPILOGUE.
// One thread per pixel. Weights from the padded transposed layout:
// 18 weights per (tt,ci) in 5 vector loads (vs 18 scalar) -> 3.6x fewer
// LSU issues. Emits precomputed bilinear sampling records for k_deform2.
// ---------------------------------------------------------------------------
__global__ void __launch_bounds__(128)
k_offconv2(const float* __restrict__ ob, int B) {
    int idx = blockIdx.x * blockDim.x + threadIdx.x;
    if (idx >= B * 196) return;
    int w = idx % 14;
    int t = idx / 14;
    int h = t % 14;
    int b = t / 14;

    float acc[18];
#pragma unroll
    for (int c = 0; c < 18; c++) acc[c] = ob[c];

    const float* pb = g_p1t + b * 196 * 32;

    for (int tt = 0; tt < 9; tt++) {
        int y  = h + tt / 3 - 1;
        int xx = w + tt % 3 - 1;
        bool ok = (y >= 0) & (y < 14) & (xx >= 0) & (xx < 14);
        if (!ok) continue;                       // zero contribution
        const float* p0 = pb + (y * 14 + xx) * 32;

#pragma unroll
        for (int cib = 0; cib < 4; cib++) {
            float4 va = *(const float4*)(p0 + cib * 8);
            float4 vb = *(const float4*)(p0 + cib * 8 + 4);
            float v[8] = {va.x, va.y, va.z, va.w, vb.x, vb.y, vb.z, vb.w};
#pragma unroll
            for (int q = 0; q < 8; q++) {
                const float* wr = g_ow2p + (tt * 32 + cib * 8 + q) * 24;
                float4 w0 = *(const float4*)(wr);
                float4 w1v = *(const float4*)(wr + 4);
                float4 w2v = *(const float4*)(wr + 8);
                float4 w3v = *(const float4*)(wr + 12);
                float2 w4 = *(const float2*)(wr + 16);
                float vv = v[q];
                acc[0]  = fmaf(w0.x,  vv, acc[0]);
                acc[1]  = fmaf(w0.y,  vv, acc[1]);
                acc[2]  = fmaf(w0.z,  vv, acc[2]);
                acc[3]  = fmaf(w0.w,  vv, acc[3]);
                acc[4]  = fmaf(w1v.x, vv, acc[4]);
                acc[5]  = fmaf(w1v.y, vv, acc[5]);
                acc[6]  = fmaf(w1v.z, vv, acc[6]);
                acc[7]  = fmaf(w1v.w, vv, acc[7]);
                acc[8]  = fmaf(w2v.x, vv, acc[8]);
                acc[9]  = fmaf(w2v.y, vv, acc[9]);
                acc[10] = fmaf(w2v.z, vv, acc[10]);
                acc[11] = fmaf(w2v.w, vv, acc[11]);
                acc[12] = fmaf(w3v.x, vv, acc[12]);
                acc[13] = fmaf(w3v.y, vv, acc[13]);
                acc[14] = fmaf(w3v.z, vv, acc[14]);
                acc[15] = fmaf(w3v.w, vv, acc[15]);
                acc[16] = fmaf(w4.x,  vv, acc[16]);
                acc[17] = fmaf(w4.y,  vv, acc[17]);
            }
        }
    }

    // ---- record epilogue: 9 taps for this pixel ----
    int bbase = b * 6272;
    int ri = idx * 9;
#pragma unroll
    for (int kk = 0; kk < 9; kk++) {
        float dy = acc[2 * kk], dx = acc[2 * kk + 1];
        float py = (float)(h + kk / 3 - 1) + dy;
        float px = (float)(w + kk % 3 - 1) + dx;
        float fy = floorf(py), fx = floorf(px);
        float ay = py - fy, ax = px - fx;
        int y0 = (int)fy, x0i = (int)fx;
        int y1 = y0 + 1,  x1i = x0i + 1;
        float vy0 = (y0  >= 0 && y0  < 14) ? 1.f : 0.f;
        float vy1 = (y1  >= 0 && y1  < 14) ? 1.f : 0.f;
        float vx0 = (x0i >= 0 && x0i < 14) ? 1.f : 0.f;
        float vx1 = (x1i >= 0 && x1i < 14) ? 1.f : 0.f;
        int yc0 = min(max(y0, 0), 13),  yc1 = min(max(y1, 0), 13);
        int xc0 = min(max(x0i, 0), 13), xc1 = min(max(x1i, 0), 13);
        g_recI[ri + kk] = make_int4(bbase + (yc0 * 14 + xc0) * 32,
                                    bbase + (yc0 * 14 + xc1) * 32,
                                    bbase + (yc1 * 14 + xc0) * 32,
                                    bbase + (yc1 * 14 + xc1) * 32);
        g_recW[ri + kk] = make_float4((1.f - ay) * (1.f - ax) * vy0 * vx0,
                                      (1.f - ay) * ax         * vy0 * vx1,
                                      ay * (1.f - ax)         * vy1 * vx0,
                                      ay * ax                 * vy1 * vx1);
    }
}

// ---------------------------------------------------------------------------
// Kernel 4: deform conv 2 (K=288 -> N=64) + relu + maxpool2.
// Block = 8 pooled pixels (M=32 quadrant rows), 128 threads = 16(n) x 8(m).
// Records batch-prefetched into smem; K in 3 chunks of 96.
// ---------------------------------------------------------------------------
#define CHUNK 96
#define SROW2 36
__global__ void __launch_bounds__(128)
k_deform2(const float* __restrict__ b2, int B) {
    __shared__ float  samp[CHUNK * SROW2];    // 13824 B
    __shared__ int4   srecI[288];             // 4608 B
    __shared__ float4 srecW[288];             // 4608 B
    __shared__ int    recbase[32];
    int tid  = threadIdx.x;
    int pix0 = blockIdx.x * 8;
    int npix = B * 49;
    int tn = tid & 15, tm = tid >> 4;
    int wid = tid >> 5, lane = tid & 31;

    if (tid < 32) {
        int m = tid, pl = m >> 2, q = m & 3;
        int pix = pix0 + pl;
        int rb = -1;
        if (pix < npix) {
            int b  = pix / 49;
            int s  = pix - b * 49;
            int h3 = s / 7, w3 = s - h3 * 7;
            int h  = h3 * 2 + (q >> 1), w = w3 * 2 + (q & 1);
            rb = (b * 196 + h * 14 + w) * 9;
        }
        recbase[m] = rb;
    }
    __syncthreads();

    // ---- batch record prefetch: 288 records x 32B, all independent ----
    for (int t = tid; t < 288; t += 128) {
        int m = t / 9, kk = t - m * 9;
        int rb = recbase[m];
        if (rb >= 0) {
            srecI[t] = g_recI[rb + kk];
            srecW[t] = g_recW[rb + kk];
        } else {
            srecI[t] = make_int4(0, 0, 0, 0);
            srecW[t] = make_float4(0.f, 0.f, 0.f, 0.f);
        }
    }

    float acc[4][4];
#pragma unroll
    for (int q = 0; q < 4; q++)
#pragma unroll
        for (int j = 0; j < 4; j++) acc[q][j] = 0.f;

    const float* wp = g_w2t + tn * 4;
    const float* sp = samp + tm * 4;

    for (int c = 0; c < 3; c++) {
        __syncthreads();

        // ---- phase 1: 96 k-rows x 32 m; deep unroll for gather MLP ----
#pragma unroll 8
        for (int i = 0; i < 24; i++) {
            int u  = i * 4 + wid;
            int kl = u >> 5;
            int m  = u & 31;
            int r  = m * 9 + c * 3 + kl;
            int4   o  = srecI[r];
            float4 wv = srecW[r];
            float val = wv.x * g_p1t[o.x + lane]
                      + wv.y * g_p1t[o.y + lane]
                      + wv.z * g_p1t[o.z + lane]
                      + wv.w * g_p1t[o.w + lane];
            samp[(kl * 32 + lane) * SROW2 + m] = val;
        }
        __syncthreads();

        // ---- phase 2: 96-k GEMM slice, 4m x 4n per thread ----
        const float* wc = wp + c * CHUNK * 64;
#pragma unroll 8
        for (int k = 0; k < CHUNK; k++) {
            float4 wv = *(const float4*)(wc + k * 64);
            float4 sv = *(const float4*)(sp + k * SROW2);
            acc[0][0] = fmaf(wv.x, sv.x, acc[0][0]);
            acc[0][1] = fmaf(wv.y, sv.x, acc[0][1]);
            acc[0][2] = fmaf(wv.z, sv.x, acc[0][2]);
            acc[0][3] = fmaf(wv.w, sv.x, acc[0][3]);
            acc[1][0] = fmaf(wv.x, sv.y, acc[1][0]);
            acc[1][1] = fmaf(wv.y, sv.y, acc[1][1]);
            acc[1][2] = fmaf(wv.z, sv.y, acc[1][2]);
            acc[1][3] = fmaf(wv.w, sv.y, acc[1][3]);
            acc[2][0] = fmaf(wv.x, sv.z, acc[2][0]);
            acc[2][1] = fmaf(wv.y, sv.z, acc[2][1]);
            acc[2][2] = fmaf(wv.z, sv.z, acc[2][2]);
            acc[2][3] = fmaf(wv.w, sv.z, acc[2][3]);
            acc[3][0] = fmaf(wv.x, sv.w, acc[3][0]);
            acc[3][1] = fmaf(wv.y, sv.w, acc[3][1]);
            acc[3][2] = fmaf(wv.z, sv.w, acc[3][2]);
            acc[3][3] = fmaf(wv.w, sv.w, acc[3][3]);
        }
    }

    // ---- epilogue: pool(max of 4 quadrants) + bias + relu ----
    int pix = pix0 + tm;
    if (pix < npix) {
        int b = pix / 49, s = pix - b * 49;
        int h3 = s / 7, w3 = s - h3 * 7;
        float* o = g_p2 + b * 3136 + h3 * 7 + w3;
#pragma unroll
        for (int j = 0; j < 4; j++) {
            int n = tn * 4 + j;
            float m = fmaxf(fmaxf(acc[0][j], acc[1][j]), fmaxf(acc[2][j], acc[3][j]));
            o[n * 49] = fmaxf(m + b2[n], 0.f);
        }
    }
}

// ---------------------------------------------------------------------------
// Kernel 5: FC (B,3136) @ (10,3136)^T + bias. One warp per (b, oc), unrolled.
// ---------------------------------------------------------------------------
__global__ void __launch_bounds__(320)
k_fc(const float* __restrict__ fw, const float* __restrict__ fb,
     float* __restrict__ out, int B) {
    int b = blockIdx.x;
    int warp = threadIdx.x >> 5;
    int lane = threadIdx.x & 31;
    const float* row = g_p2 + b * 3136;
    const float* wr  = fw + warp * 3136;
    float s = 0.f;
    int i = lane * 4;
#pragma unroll 4
    for (int it = 0; it < 24; it++, i += 128) {
        float4 a = *(const float4*)(row + i);
        float4 w = *(const float4*)(wr + i);
        s = fmaf(a.x, w.x, s); s = fmaf(a.y, w.y, s);
        s = fmaf(a.z, w.z, s); s = fmaf(a.w, w.w, s);
    }
    if (i < 3136) {
        float4 a = *(const float4*)(row + i);
        float4 w = *(const float4*)(wr + i);
        s = fmaf(a.x, w.x, s); s = fmaf(a.y, w.y, s);
        s = fmaf(a.z, w.z, s); s = fmaf(a.w, w.w, s);
    }
#pragma unroll
    for (int off = 16; off; off >>= 1) s += __shfl_xor_sync(0xffffffffu, s, off);
    if (lane == 0) out[b * 10 + warp] = s + fb[warp];
}

// ---------------------------------------------------------------------------
extern "C" void kernel_launch(void* const* d_in, const int* in_sizes, int n_in,
                              void* d_out, int out_size) {
    const float* x      = (const float*)d_in[0];
    const float* off_w1 = (const float*)d_in[1];
    const float* off_b1 = (const float*)d_in[2];
    const float* w1     = (const float*)d_in[3];
    const float* b1     = (const float*)d_in[4];
    const float* off_w2 = (const float*)d_in[5];
    const float* off_b2 = (const float*)d_in[6];
    const float* w2     = (const float*)d_in[7];
    const float* b2     = (const float*)d_in[8];
    const float* fc_w   = (const float*)d_in[9];
    const float* fc_b   = (const float*)d_in[10];
    float* out = (float*)d_out;

    int B = in_sizes[0] / 784;
    if (B > BMAX) B = BMAX;

    k_prep<<<(64 * 288 + 288 * 24 + 255) / 256, 256>>>(w2, off_w2);
    k_stage1<<<(B * 784 + 127) / 128, 128>>>(x, off_w1, off_b1, w1, b1, B);
    k_offconv2<<<(B * 196 + 127) / 128, 128>>>(off_b2, B);
    k_deform2<<<(B * 49 + 7) / 8, 128>>>(b2, B);
    k_fc<<<B, 320>>>(fc_w, fc_b, out, B);
}